// round 2
// baseline (speedup 1.0000x reference)
#include <cuda_runtime.h>
#include <math.h>

#define BATCH  4
#define LSEQ   8192
#define NHEADS 8
#define HEAD   64
#define NV     128      // n_vars (rows of the per-tile attention)
#define PP     64       // patches per variable = L / NV
#define DMODEL 512      // NHEADS * HEAD

#define XP 65           // padded row stride for 64-wide tiles (conflict-free column access)
#define AP 129          // padded row stride for 128-wide tile

// smem floats:
//  Xs 128*65, Qs 128*65, Ks 128*65, W1s 64*65, W2s 64*65, As 128*129,
//  b1s 64, b2s 64, red 512 (max/sum partials), rowinv 128
#define SMEM_FLOATS (3*NV*XP + 2*HEAD*XP + NV*AP + HEAD + HEAD + 512 + NV)
#define SMEM_BYTES  (SMEM_FLOATS * 4)

__global__ __launch_bounds__(256, 1)
void sg_kernel(const float* __restrict__ x,
               const float* __restrict__ w1, const float* __restrict__ b1,
               const float* __restrict__ w2, const float* __restrict__ b2,
               float* __restrict__ out)
{
    extern __shared__ float sm[];
    float* Xs  = sm;                    // [128][65]
    float* Qs  = Xs  + NV * XP;         // [128][65]
    float* Ks  = Qs  + NV * XP;         // [128][65]
    float* W1s = Ks  + NV * XP;         // [64][65]
    float* W2s = W1s + HEAD * XP;       // [64][65]
    float* As  = W2s + HEAD * XP;       // [128][129]
    float* b1s = As  + NV * AP;         // [64]
    float* b2s = b1s + HEAD;            // [64]
    float* red = b2s + HEAD;            // [512] (max partials [0..255], sum partials [256..511])
    float* rowinv = red + 512;          // [128]

    const int tid = threadIdx.x;
    const int bid = blockIdx.x;
    const int b   = bid / (NHEADS * PP);
    const int rem = bid % (NHEADS * PP);
    const int h   = rem / PP;
    const int p   = rem % PP;

    // ---- Load weights + biases + X tile into smem ----
    for (int idx = tid; idx < HEAD * HEAD; idx += 256) {
        int r = idx >> 6, c = idx & 63;
        W1s[r * XP + c] = w1[idx];
        W2s[r * XP + c] = w2[idx];
    }
    if (tid < HEAD) { b1s[tid] = b1[tid]; b2s[tid] = b2[tid]; }

    // X[i][d] = x[b, i*PP + p, h*HEAD + d]
    const float* xbase = x + ((size_t)b * LSEQ + p) * DMODEL + h * HEAD;
    for (int idx = tid; idx < NV * HEAD; idx += 256) {
        int i = idx >> 6, d = idx & 63;
        Xs[i * XP + d] = xbase[(size_t)i * (PP * DMODEL) + d];
    }
    __syncthreads();

    const int tx = tid & 15;   // 16 columns of thread grid
    const int ty = tid >> 4;   // 16 rows of thread grid

    // ---- Phase B: Q = X W1^T + b1 ; K = X W2^T + b2 ----
    {
        float aq[8][4], ak[8][4];
        #pragma unroll
        for (int a = 0; a < 8; a++)
            #pragma unroll
            for (int c = 0; c < 4; c++) { aq[a][c] = 0.f; ak[a][c] = 0.f; }

        #pragma unroll 4
        for (int e = 0; e < HEAD; e++) {
            float xv[8], w1v[4], w2v[4];
            #pragma unroll
            for (int a = 0; a < 8; a++) xv[a] = Xs[(ty + 16 * a) * XP + e];
            #pragma unroll
            for (int c = 0; c < 4; c++) {
                w1v[c] = W1s[(tx + 16 * c) * XP + e];
                w2v[c] = W2s[(tx + 16 * c) * XP + e];
            }
            #pragma unroll
            for (int a = 0; a < 8; a++)
                #pragma unroll
                for (int c = 0; c < 4; c++) {
                    aq[a][c] = fmaf(xv[a], w1v[c], aq[a][c]);
                    ak[a][c] = fmaf(xv[a], w2v[c], ak[a][c]);
                }
        }
        #pragma unroll
        for (int a = 0; a < 8; a++)
            #pragma unroll
            for (int c = 0; c < 4; c++) {
                int i = ty + 16 * a, d = tx + 16 * c;
                Qs[i * XP + d] = aq[a][c] + b1s[d];
                Ks[i * XP + d] = ak[a][c] + b2s[d];
            }
    }
    __syncthreads();

    // ---- Phase C: S = Q K^T ; gelu(exact) ; stage into As ----
    {
        float acc[8][8];
        #pragma unroll
        for (int a = 0; a < 8; a++)
            #pragma unroll
            for (int bb = 0; bb < 8; bb++) acc[a][bb] = 0.f;

        #pragma unroll 4
        for (int e = 0; e < HEAD; e++) {
            float qv[8], kv[8];
            #pragma unroll
            for (int a = 0; a < 8; a++) qv[a] = Qs[(ty + 16 * a) * XP + e];
            #pragma unroll
            for (int bb = 0; bb < 8; bb++) kv[bb] = Ks[(tx + 16 * bb) * XP + e];
            #pragma unroll
            for (int a = 0; a < 8; a++)
                #pragma unroll
                for (int bb = 0; bb < 8; bb++)
                    acc[a][bb] = fmaf(qv[a], kv[bb], acc[a][bb]);
        }
        #pragma unroll
        for (int a = 0; a < 8; a++)
            #pragma unroll
            for (int bb = 0; bb < 8; bb++) {
                float s = acc[a][bb];
                float g = 0.5f * s * (1.0f + erff(s * 0.70710678118654752f));
                As[(ty + 16 * a) * AP + (tx + 16 * bb)] = g;
            }
    }
    __syncthreads();

    // ---- Softmax staging: As <- exp(g - rowmax), rowinv <- 1/rowsum ----
    {
        int r = tid >> 1, half = tid & 1;
        int base = r * AP + half * 64;
        float m = -1e30f;
        #pragma unroll 8
        for (int jj = 0; jj < 64; jj++) m = fmaxf(m, As[base + jj]);
        red[tid] = m;
        __syncthreads();
        m = fmaxf(red[tid & ~1], red[tid | 1]);
        float s = 0.f;
        #pragma unroll 8
        for (int jj = 0; jj < 64; jj++) {
            float e = __expf(As[base + jj] - m);
            As[base + jj] = e;
            s += e;
        }
        red[256 + tid] = s;
        __syncthreads();
        if (half == 0) rowinv[r] = 1.0f / (red[256 + tid] + red[256 + tid + 1]);
    }
    __syncthreads();

    // ---- Phase D: Y = A X, scale by rowinv, store ----
    {
        float acc[8][4];
        #pragma unroll
        for (int a = 0; a < 8; a++)
            #pragma unroll
            for (int c = 0; c < 4; c++) acc[a][c] = 0.f;

        #pragma unroll 4
        for (int j = 0; j < NV; j++) {
            float av[8], xv[4];
            #pragma unroll
            for (int a = 0; a < 8; a++) av[a] = As[(ty + 16 * a) * AP + j];
            #pragma unroll
            for (int c = 0; c < 4; c++) xv[c] = Xs[j * XP + (tx + 16 * c)];
            #pragma unroll
            for (int a = 0; a < 8; a++)
                #pragma unroll
                for (int c = 0; c < 4; c++)
                    acc[a][c] = fmaf(av[a], xv[c], acc[a][c]);
        }

        // out[b, i*PP + p, h*HEAD + d]
        #pragma unroll
        for (int a = 0; a < 8; a++) {
            int i = ty + 16 * a;
            float inv = rowinv[i];
            size_t ob = ((size_t)b * LSEQ + (size_t)i * PP + p) * DMODEL + h * HEAD;
            #pragma unroll
            for (int c = 0; c < 4; c++) {
                int d = tx + 16 * c;
                out[ob + d] = acc[a][c] * inv;
            }
        }
    }
}

extern "C" void kernel_launch(void* const* d_in, const int* in_sizes, int n_in,
                              void* d_out, int out_size)
{
    const float* x  = (const float*)d_in[0];
    const float* w1 = (const float*)d_in[1];
    const float* b1 = (const float*)d_in[2];
    const float* w2 = (const float*)d_in[3];
    const float* b2 = (const float*)d_in[4];
    float* out = (float*)d_out;

    cudaFuncSetAttribute(sg_kernel, cudaFuncAttributeMaxDynamicSharedMemorySize, SMEM_BYTES);
    sg_kernel<<<BATCH * NHEADS * PP, 256, SMEM_BYTES>>>(x, w1, b1, w2, b2, out);
}

// round 3
// speedup vs baseline: 1.7978x; 1.7978x over previous
#include <cuda_runtime.h>
#include <math.h>

#define BATCH  4
#define LSEQ   8192
#define NHEADS 8
#define HEAD   64
#define NV     128
#define PP     64
#define DMODEL 512

#define XS   68     // stride for 64-wide tiles: 68%32=4 -> bank=4r+c, conflict-free frags
#define APAD 132    // stride for 128-wide tile: 132%32=4

#define SMEM_FLOATS (3*NV*XS + 2*HEAD*XS + NV*APAD + HEAD + HEAD + 512 + NV)
#define SMEM_BYTES  (SMEM_FLOATS * 4)

__device__ __forceinline__ float to_tf32(float x) {
    float y;
    asm("cvt.rna.tf32.f32 %0, %1;" : "=f"(y) : "f"(x));
    return y;
}

__device__ __forceinline__ void mma8(float c[4], const float a[4], const float b[2]) {
    asm volatile(
        "mma.sync.aligned.m16n8k8.row.col.f32.tf32.tf32.f32 "
        "{%0,%1,%2,%3}, {%4,%5,%6,%7}, {%8,%9}, {%0,%1,%2,%3};"
        : "+f"(c[0]), "+f"(c[1]), "+f"(c[2]), "+f"(c[3])
        : "r"(__float_as_uint(a[0])), "r"(__float_as_uint(a[1])),
          "r"(__float_as_uint(a[2])), "r"(__float_as_uint(a[3])),
          "r"(__float_as_uint(b[0])), "r"(__float_as_uint(b[1])));
}

__global__ __launch_bounds__(256, 1)
void sg_tc_kernel(const float* __restrict__ x,
                  const float* __restrict__ w1, const float* __restrict__ b1,
                  const float* __restrict__ w2, const float* __restrict__ b2,
                  float* __restrict__ out)
{
    extern __shared__ float sm[];
    float* Xs  = sm;                    // [128][68]  tf32-rounded X tile
    float* Qs  = Xs  + NV * XS;         // [128][68]
    float* Ks  = Qs  + NV * XS;         // [128][68]
    float* W1s = Ks  + NV * XS;         // [64][68]
    float* W2s = W1s + HEAD * XS;       // [64][68]
    float* As  = W2s + HEAD * XS;       // [128][132]
    float* b1s = As  + NV * APAD;       // [64]
    float* b2s = b1s + HEAD;            // [64]
    float* red = b2s + HEAD;            // [512]
    float* rowinv = red + 512;          // [128]

    const int tid = threadIdx.x;
    const int bid = blockIdx.x;
    const int b   = bid / (NHEADS * PP);
    const int rem = bid % (NHEADS * PP);
    const int h   = rem / PP;
    const int p   = rem % PP;

    // ---- Load weights/bias/X, rounding MMA operands to tf32 at write ----
    for (int idx = tid; idx < HEAD * HEAD; idx += 256) {
        int r = idx >> 6, c = idx & 63;
        W1s[r * XS + c] = to_tf32(w1[idx]);
        W2s[r * XS + c] = to_tf32(w2[idx]);
    }
    if (tid < HEAD) { b1s[tid] = b1[tid]; b2s[tid] = b2[tid]; }

    const float* xbase = x + ((size_t)b * LSEQ + p) * DMODEL + h * HEAD;
    for (int idx = tid; idx < NV * HEAD; idx += 256) {
        int i = idx >> 6, d = idx & 63;
        Xs[i * XS + d] = to_tf32(xbase[(size_t)i * (PP * DMODEL) + d]);
    }
    __syncthreads();

    const int warp = tid >> 5;
    const int lane = tid & 31;
    const int lr = lane >> 2;   // quad row 0..7
    const int lc = lane & 3;    // quad col 0..3

    // ---- Phase B: Q = X W1^T + b1, K = X W2^T + b2 (tensor) ----
    {
        float cq[8][4], ck[8][4];
        #pragma unroll
        for (int n = 0; n < 8; n++)
            #pragma unroll
            for (int q = 0; q < 4; q++) { cq[n][q] = 0.f; ck[n][q] = 0.f; }

        const int m0 = warp * 16;
        const int rA0 = (m0 + lr) * XS, rA1 = (m0 + lr + 8) * XS;
        #pragma unroll
        for (int k = 0; k < 8; k++) {
            const int e0 = k * 8;
            float a[4] = { Xs[rA0 + e0 + lc],     Xs[rA1 + e0 + lc],
                           Xs[rA0 + e0 + lc + 4], Xs[rA1 + e0 + lc + 4] };
            #pragma unroll
            for (int n = 0; n < 8; n++) {
                const int rB = (n * 8 + lr) * XS + e0 + lc;
                float bq[2] = { W1s[rB], W1s[rB + 4] };
                mma8(cq[n], a, bq);
                float bk[2] = { W2s[rB], W2s[rB + 4] };
                mma8(ck[n], a, bk);
            }
        }
        #pragma unroll
        for (int n = 0; n < 8; n++) {
            const int d0 = n * 8 + 2 * lc;
            const float q0 = b1s[d0], q1 = b1s[d0 + 1];
            const float k0 = b2s[d0], k1 = b2s[d0 + 1];
            const int i0 = (m0 + lr) * XS + d0, i1 = (m0 + lr + 8) * XS + d0;
            *(float2*)(Qs + i0) = make_float2(to_tf32(cq[n][0] + q0), to_tf32(cq[n][1] + q1));
            *(float2*)(Qs + i1) = make_float2(to_tf32(cq[n][2] + q0), to_tf32(cq[n][3] + q1));
            *(float2*)(Ks + i0) = make_float2(to_tf32(ck[n][0] + k0), to_tf32(ck[n][1] + k1));
            *(float2*)(Ks + i1) = make_float2(to_tf32(ck[n][2] + k0), to_tf32(ck[n][3] + k1));
        }
    }
    __syncthreads();

    // ---- Phase C: S = Q K^T (tensor), gelu, stage into As ----
    {
        float cs[2][8][4];
        #pragma unroll
        for (int m = 0; m < 2; m++)
            #pragma unroll
            for (int n = 0; n < 8; n++)
                #pragma unroll
                for (int q = 0; q < 4; q++) cs[m][n][q] = 0.f;

        const int r0 = (warp & 3) * 32;
        const int c0 = (warp >> 2) * 64;
        #pragma unroll
        for (int k = 0; k < 8; k++) {
            const int e0 = k * 8;
            const int q0 = (r0 + lr) * XS + e0 + lc, q1 = (r0 + 16 + lr) * XS + e0 + lc;
            float a0[4] = { Qs[q0], Qs[q0 + 8 * XS], Qs[q0 + 4], Qs[q0 + 8 * XS + 4] };
            float a1[4] = { Qs[q1], Qs[q1 + 8 * XS], Qs[q1 + 4], Qs[q1 + 8 * XS + 4] };
            #pragma unroll
            for (int n = 0; n < 8; n++) {
                const int rB = (c0 + n * 8 + lr) * XS + e0 + lc;
                float bf[2] = { Ks[rB], Ks[rB + 4] };
                mma8(cs[0][n], a0, bf);
                mma8(cs[1][n], a1, bf);
            }
        }
        // gelu (exact) and store
        #pragma unroll
        for (int m = 0; m < 2; m++) {
            const int rr0 = r0 + m * 16 + lr, rr1 = rr0 + 8;
            #pragma unroll
            for (int n = 0; n < 8; n++) {
                const int col = c0 + n * 8 + 2 * lc;
                float g0 = cs[m][n][0], g1 = cs[m][n][1], g2 = cs[m][n][2], g3 = cs[m][n][3];
                g0 = 0.5f * g0 * (1.0f + erff(g0 * 0.70710678118654752f));
                g1 = 0.5f * g1 * (1.0f + erff(g1 * 0.70710678118654752f));
                g2 = 0.5f * g2 * (1.0f + erff(g2 * 0.70710678118654752f));
                g3 = 0.5f * g3 * (1.0f + erff(g3 * 0.70710678118654752f));
                *(float2*)(As + rr0 * APAD + col) = make_float2(g0, g1);
                *(float2*)(As + rr1 * APAD + col) = make_float2(g2, g3);
            }
        }
    }
    __syncthreads();

    // ---- Softmax: As <- tf32(exp(g - rowmax)), rowinv <- 1/rowsum ----
    {
        const int r = tid >> 1, half = tid & 1;
        const int base = r * APAD + half * 64;
        float m = -1e30f;
        #pragma unroll 8
        for (int jj = 0; jj < 64; jj++) m = fmaxf(m, As[base + jj]);
        red[tid] = m;
        __syncthreads();
        m = fmaxf(red[tid & ~1], red[tid | 1]);
        float s = 0.f;
        #pragma unroll 8
        for (int jj = 0; jj < 64; jj++) {
            float e = __expf(As[base + jj] - m);
            As[base + jj] = to_tf32(e);
            s += e;
        }
        red[256 + tid] = s;
        __syncthreads();
        if (half == 0) rowinv[r] = 1.0f / (red[256 + tid] + red[256 + tid + 1]);
    }
    __syncthreads();

    // ---- Phase D: Y = P X (tensor), scale by rowinv, store ----
    {
        float cy[8][4];
        #pragma unroll
        for (int n = 0; n < 8; n++)
            #pragma unroll
            for (int q = 0; q < 4; q++) cy[n][q] = 0.f;

        const int m0 = warp * 16;
        #pragma unroll
        for (int k = 0; k < 16; k++) {
            const int j0 = k * 8;
            const int pA = (m0 + lr) * APAD + j0 + lc;
            float a[4] = { As[pA], As[pA + 8 * APAD], As[pA + 4], As[pA + 8 * APAD + 4] };
            #pragma unroll
            for (int n = 0; n < 8; n++) {
                const int d0 = n * 8;
                float bf[2] = { Xs[(j0 + lc) * XS + d0 + lr],
                                Xs[(j0 + lc + 4) * XS + d0 + lr] };
                mma8(cy[n], a, bf);
            }
        }

        const float inv0 = rowinv[m0 + lr];
        const float inv1 = rowinv[m0 + lr + 8];
        const size_t ob0 = ((size_t)b * LSEQ + (size_t)(m0 + lr) * PP + p) * DMODEL + h * HEAD;
        const size_t ob1 = ((size_t)b * LSEQ + (size_t)(m0 + lr + 8) * PP + p) * DMODEL + h * HEAD;
        #pragma unroll
        for (int n = 0; n < 8; n++) {
            const int d0 = n * 8 + 2 * lc;
            *(float2*)(out + ob0 + d0) = make_float2(cy[n][0] * inv0, cy[n][1] * inv0);
            *(float2*)(out + ob1 + d0) = make_float2(cy[n][2] * inv1, cy[n][3] * inv1);
        }
    }
}

extern "C" void kernel_launch(void* const* d_in, const int* in_sizes, int n_in,
                              void* d_out, int out_size)
{
    const float* x  = (const float*)d_in[0];
    const float* w1 = (const float*)d_in[1];
    const float* b1 = (const float*)d_in[2];
    const float* w2 = (const float*)d_in[3];
    const float* b2 = (const float*)d_in[4];
    float* out = (float*)d_out;

    cudaFuncSetAttribute(sg_tc_kernel, cudaFuncAttributeMaxDynamicSharedMemorySize, SMEM_BYTES);
    sg_tc_kernel<<<BATCH * NHEADS * PP, 256, SMEM_BYTES>>>(x, w1, b1, w2, b2, out);
}